// round 5
// baseline (speedup 1.0000x reference)
#include <cuda_runtime.h>
#include <stdint.h>

// dice_shape_loss: mean over 64*1*448*448 = 12,845,056 elements of
//   a = -(y*max(log p,-100) + (1-y)*max(log(1-p),-100));  out = mean(a*(1+shapeloss))
// HBM-bound streaming reduction: 154.1 MB read, 4 B write.
// R5: register-double-buffered loads (3 LDG.128 always in flight per thread),
//     __ldcs streaming. Finalize via memset node + per-block atomicAdd
//     (R2-proven control structure; last-block scheme dropped to de-risk).

#define LOG_CLAMP (-100.0f)

#define NBLOCKS  (148 * 6)
#define NTHREADS 256

__device__ __forceinline__ float elem_loss(float t, float p, float s) {
    float lp = fmaxf(__logf(p), LOG_CLAMP);
    float lq = fmaxf(__logf(1.0f - p), LOG_CLAMP);
    // a = -(t*lp + (1-t)*lq)   (t is exactly 0.0 or 1.0)
    float a = -fmaf(t, lp - lq, lq);
    return fmaf(a, s, a);   // a*s + a
}

__device__ __forceinline__ float quad_loss(float4 t, float4 p, float4 s) {
    float acc;
    acc  = elem_loss(t.x, p.x, s.x);
    acc += elem_loss(t.y, p.y, s.y);
    acc += elem_loss(t.z, p.z, s.z);
    acc += elem_loss(t.w, p.w, s.w);
    return acc;
}

__global__ void __launch_bounds__(NTHREADS)
bce_shape_reduce_kernel(const float4* __restrict__ yt,
                        const float4* __restrict__ yp,
                        const float4* __restrict__ sl,
                        float* __restrict__ out,
                        int n4, float inv_n) {
    float acc = 0.0f;
    int idx    = blockIdx.x * blockDim.x + threadIdx.x;
    int stride = gridDim.x * blockDim.x;

    // Software-pipelined grid-stride loop: issue next iteration's 3 LDG.128
    // before consuming the current one -> memory pipe never drains.
    if (idx < n4) {
        float4 t0 = __ldcs(yt + idx);
        float4 p0 = __ldcs(yp + idx);
        float4 s0 = __ldcs(sl + idx);
        for (int j = idx + stride; j < n4; j += stride) {
            float4 t1 = __ldcs(yt + j);
            float4 p1 = __ldcs(yp + j);
            float4 s1 = __ldcs(sl + j);
            acc += quad_loss(t0, p0, s0);
            t0 = t1; p0 = p1; s0 = s1;
        }
        acc += quad_loss(t0, p0, s0);
    }

    // intra-block reduction
    #pragma unroll
    for (int o = 16; o > 0; o >>= 1)
        acc += __shfl_down_sync(0xFFFFFFFFu, acc, o);

    __shared__ float warp_sums[NTHREADS / 32];
    int lane = threadIdx.x & 31;
    int wid  = threadIdx.x >> 5;
    if (lane == 0) warp_sums[wid] = acc;
    __syncthreads();

    if (wid == 0) {
        float v = (lane < (NTHREADS / 32)) ? warp_sums[lane] : 0.0f;
        #pragma unroll
        for (int o = 4; o > 0; o >>= 1)
            v += __shfl_down_sync(0xFFFFFFFFu, v, o);
        if (lane == 0)
            atomicAdd(out, v * inv_n);
    }
}

extern "C" void kernel_launch(void* const* d_in, const int* in_sizes, int n_in,
                              void* d_out, int out_size) {
    const float4* yt = (const float4*)d_in[0];  // y_true
    const float4* yp = (const float4*)d_in[1];  // y_pred
    const float4* sl = (const float4*)d_in[2];  // shapeloss
    float* out = (float*)d_out;

    int n  = in_sizes[0];            // 12,845,056
    int n4 = n >> 2;                 // 3,211,264
    float inv_n = 1.0f / (float)n;

    cudaMemsetAsync(out, 0, sizeof(float));   // capture-legal memset node

    bce_shape_reduce_kernel<<<NBLOCKS, NTHREADS>>>(yt, yp, sl, out, n4, inv_n);
}

// round 7
// speedup vs baseline: 1.0167x; 1.0167x over previous
#include <cuda_runtime.h>
#include <stdint.h>

// dice_shape_loss: mean over 64*1*448*448 = 12,845,056 elements of
//   a = -(y*max(log p,-100) + (1-y)*max(log(1-p),-100));  out = mean(a*(1+shapeloss))
// HBM-bound streaming reduction: 154.1 MB read, 4 B write.
// R7: R5 pipelined streaming body (measured 26.85us kernel, at the ~5.9TB/s
// pattern ceiling) + R2-style zero kernel (measured 1.31us node cost, cheaper
// than a memset node's 2.34us) + per-block atomicAdd. No device globals.

#define LOG_CLAMP (-100.0f)

#define NBLOCKS  (148 * 6)
#define NTHREADS 256

__global__ void zero_out_kernel(float* out) {
    if (threadIdx.x == 0) out[0] = 0.0f;
}

__device__ __forceinline__ float elem_loss(float t, float p, float s) {
    float lp = fmaxf(__logf(p), LOG_CLAMP);
    float lq = fmaxf(__logf(1.0f - p), LOG_CLAMP);
    // a = -(t*lp + (1-t)*lq)   (t is exactly 0.0 or 1.0)
    float a = -fmaf(t, lp - lq, lq);
    return fmaf(a, s, a);   // a*s + a
}

__device__ __forceinline__ float quad_loss(float4 t, float4 p, float4 s) {
    float acc;
    acc  = elem_loss(t.x, p.x, s.x);
    acc += elem_loss(t.y, p.y, s.y);
    acc += elem_loss(t.z, p.z, s.z);
    acc += elem_loss(t.w, p.w, s.w);
    return acc;
}

__global__ void __launch_bounds__(NTHREADS)
bce_shape_reduce_kernel(const float4* __restrict__ yt,
                        const float4* __restrict__ yp,
                        const float4* __restrict__ sl,
                        float* __restrict__ out,
                        int n4, float inv_n) {
    float acc = 0.0f;
    int idx    = blockIdx.x * blockDim.x + threadIdx.x;
    int stride = gridDim.x * blockDim.x;

    // Software-pipelined grid-stride loop (R5 body, measured 26.85us).
    if (idx < n4) {
        float4 t0 = __ldcs(yt + idx);
        float4 p0 = __ldcs(yp + idx);
        float4 s0 = __ldcs(sl + idx);
        for (int j = idx + stride; j < n4; j += stride) {
            float4 t1 = __ldcs(yt + j);
            float4 p1 = __ldcs(yp + j);
            float4 s1 = __ldcs(sl + j);
            acc += quad_loss(t0, p0, s0);
            t0 = t1; p0 = p1; s0 = s1;
        }
        acc += quad_loss(t0, p0, s0);
    }

    // intra-block reduction
    #pragma unroll
    for (int o = 16; o > 0; o >>= 1)
        acc += __shfl_down_sync(0xFFFFFFFFu, acc, o);

    __shared__ float warp_sums[NTHREADS / 32];
    int lane = threadIdx.x & 31;
    int wid  = threadIdx.x >> 5;
    if (lane == 0) warp_sums[wid] = acc;
    __syncthreads();

    if (wid == 0) {
        float v = (lane < (NTHREADS / 32)) ? warp_sums[lane] : 0.0f;
        #pragma unroll
        for (int o = 4; o > 0; o >>= 1)
            v += __shfl_down_sync(0xFFFFFFFFu, v, o);
        if (lane == 0)
            atomicAdd(out, v * inv_n);
    }
}

extern "C" void kernel_launch(void* const* d_in, const int* in_sizes, int n_in,
                              void* d_out, int out_size) {
    const float4* yt = (const float4*)d_in[0];  // y_true
    const float4* yp = (const float4*)d_in[1];  // y_pred
    const float4* sl = (const float4*)d_in[2];  // shapeloss
    float* out = (float*)d_out;

    int n  = in_sizes[0];            // 12,845,056
    int n4 = n >> 2;                 // 3,211,264
    float inv_n = 1.0f / (float)n;

    zero_out_kernel<<<1, 32>>>(out);
    bce_shape_reduce_kernel<<<NBLOCKS, NTHREADS>>>(yt, yp, sl, out, n4, inv_n);
}